// round 1
// baseline (speedup 1.0000x reference)
#include <cuda_runtime.h>
#include <math.h>

#define N    8192
#define FIN  256
#define FOUT 128
#define ALPHA 0.2f

#define NSPLIT 4
#define BI 64      // i-rows per block in attention kernel
#define TJ 32      // j-tile

// Scratch (device globals: allocation-free per harness rules)
__device__ __align__(16) float g_Wh[N * FOUT];          // 4 MB
__device__ float g_s1[N];
__device__ float g_s2[N];
__device__ __align__(16) float g_pnum[NSPLIT][N * FOUT]; // 16 MB
__device__ float g_pden[NSPLIT][N];

// ---------------------------------------------------------------------------
// exp(x) without MUFU: 2^(x*log2e) via magic-number round + degree-6 poly.
// Valid for |x| < ~80; our scores are bounded |x| <= ~8. rel err ~1e-7.
// ---------------------------------------------------------------------------
__device__ __forceinline__ float fast_exp(float x) {
    float t = x * 1.4426950408889634f;           // x * log2(e)
    float magic = t + 12582912.0f;               // 1.5 * 2^23 : round to nearest
    int   ik = __float_as_int(magic) - 0x4B400000;
    float k = magic - 12582912.0f;
    float f = t - k;                              // f in [-0.5, 0.5]
    // 2^f = exp(f*ln2), Taylor-6 in (f*ln2)
    float p = 0.0001540353039338161f;
    p = fmaf(p, f, 0.0013333558146428443f);
    p = fmaf(p, f, 0.009618129107628477f);
    p = fmaf(p, f, 0.05550410866482158f);
    p = fmaf(p, f, 0.2402265069591007f);
    p = fmaf(p, f, 0.6931471805599453f);
    p = fmaf(p, f, 1.0f);
    float scale = __int_as_float((ik + 127) << 23);
    return scale * p;
}

// ---------------------------------------------------------------------------
// Kernel 1: Wh = x @ W^T.  Block = 16 rows of x, 128 threads (one per out col)
// ---------------------------------------------------------------------------
__global__ __launch_bounds__(128) void k_wh(const float* __restrict__ x,
                                            const float* __restrict__ W) {
    __shared__ __align__(16) float xs[16][FIN];   // 16 KB
    const int f  = threadIdx.x;
    const int r0 = blockIdx.x * 16;

    for (int idx = f; idx < 16 * FIN; idx += 128) {
        xs[idx / FIN][idx % FIN] = x[(r0 + idx / FIN) * FIN + (idx % FIN)];
    }
    __syncthreads();

    float acc[16];
    #pragma unroll
    for (int r = 0; r < 16; r++) acc[r] = 0.0f;

    const float4* Wrow = reinterpret_cast<const float4*>(W + f * FIN);
    #pragma unroll 4
    for (int k4 = 0; k4 < FIN / 4; k4++) {
        float4 wv = Wrow[k4];              // thread-private stream, L1-resident W
        #pragma unroll
        for (int r = 0; r < 16; r++) {
            float4 xv = *reinterpret_cast<const float4*>(&xs[r][k4 * 4]); // broadcast
            acc[r] = fmaf(xv.x, wv.x, acc[r]);
            acc[r] = fmaf(xv.y, wv.y, acc[r]);
            acc[r] = fmaf(xv.z, wv.z, acc[r]);
            acc[r] = fmaf(xv.w, wv.w, acc[r]);
        }
    }
    #pragma unroll
    for (int r = 0; r < 16; r++) g_Wh[(r0 + r) * FOUT + f] = acc[r];
}

// ---------------------------------------------------------------------------
// Kernel 1b: s1[i] = Wh[i]·a1, s2[i] = Wh[i]·a2. One block per row.
// ---------------------------------------------------------------------------
__global__ __launch_bounds__(128) void k_s(const float* __restrict__ a) {
    const int row = blockIdx.x;
    const int f   = threadIdx.x;
    float w  = g_Wh[row * FOUT + f];
    float p1 = w * a[f];
    float p2 = w * a[FOUT + f];
    #pragma unroll
    for (int o = 16; o > 0; o >>= 1) {
        p1 += __shfl_down_sync(0xffffffffu, p1, o);
        p2 += __shfl_down_sync(0xffffffffu, p2, o);
    }
    __shared__ float r1[4], r2[4];
    if ((f & 31) == 0) { r1[f >> 5] = p1; r2[f >> 5] = p2; }
    __syncthreads();
    if (f == 0) {
        g_s1[row] = r1[0] + r1[1] + r1[2] + r1[3];
        g_s2[row] = r2[0] + r2[1] + r2[2] + r2[3];
    }
}

// ---------------------------------------------------------------------------
// Kernel 2: partial attention GEMM.
// Block = 64 i-rows x full FOUT, over a 2048-wide j range (blockIdx.y split).
// 128 threads, 8x8 register micro-tile. No atomics (deterministic).
// ---------------------------------------------------------------------------
__global__ __launch_bounds__(128) void k_attn(const int* __restrict__ adj) {
    __shared__ __align__(16) float whs[TJ][FOUT];   // 16 KB  Wh tile
    __shared__ __align__(16) float wts[TJ][BI];     //  8 KB  weights (transposed)
    __shared__ float s1s[BI];
    __shared__ float s2s[TJ];

    const int tid   = threadIdx.x;
    const int i0    = blockIdx.x * BI;
    const int split = blockIdx.y;
    const int tr = tid >> 4;          // 0..7  (row group of 8)
    const int tc = tid & 15;          // 0..15 (feature group of 8)

    float acc[8][8];
    #pragma unroll
    for (int r = 0; r < 8; r++)
        #pragma unroll
        for (int c = 0; c < 8; c++) acc[r][c] = 0.0f;

    float myden = 0.0f;

    if (tid < BI) s1s[tid] = g_s1[i0 + tid];
    __syncthreads();

    const int jbeg = split * (N / NSPLIT);
    const int jend = jbeg + (N / NSPLIT);

    for (int j0 = jbeg; j0 < jend; j0 += TJ) {
        __syncthreads();  // previous tile's whs/wts fully consumed

        if (tid < TJ) s2s[tid] = g_s2[j0 + tid];

        // load Wh tile (coalesced float4)
        {
            const float4* src = reinterpret_cast<const float4*>(g_Wh + (size_t)j0 * FOUT);
            float4* dst = reinterpret_cast<float4*>(&whs[0][0]);
            #pragma unroll
            for (int u = 0; u < 8; u++) dst[tid + u * 128] = src[tid + u * 128];
        }
        __syncthreads();  // s2s + whs ready

        // compute masked exp weights; lanes sweep jj for coalesced adj reads
        {
            const int jj = tid & 31;
            const int wrp = tid >> 5;
            #pragma unroll 4
            for (int u = 0; u < 16; u++) {
                const int r = u * 4 + wrp;
                int ad = adj[(size_t)(i0 + r) * N + (j0 + jj)];
                float t = s1s[r] + s2s[jj];
                t = t > 0.0f ? t : ALPHA * t;
                float w = (ad > 0) ? fast_exp(t) : 0.0f;
                wts[jj][r] = w;
            }
        }
        __syncthreads();  // wts ready

        // partial denominators
        if (tid < BI) {
            float d = 0.0f;
            #pragma unroll
            for (int jj = 0; jj < TJ; jj++) d += wts[jj][tid];
            myden += d;
        }

        // 8x8 outer-product accumulation
        #pragma unroll
        for (int jj = 0; jj < TJ; jj++) {
            float wr[8], hr[8];
            *reinterpret_cast<float4*>(&wr[0]) = *reinterpret_cast<const float4*>(&wts[jj][tr * 8]);
            *reinterpret_cast<float4*>(&wr[4]) = *reinterpret_cast<const float4*>(&wts[jj][tr * 8 + 4]);
            *reinterpret_cast<float4*>(&hr[0]) = *reinterpret_cast<const float4*>(&whs[jj][tc * 8]);
            *reinterpret_cast<float4*>(&hr[4]) = *reinterpret_cast<const float4*>(&whs[jj][tc * 8 + 4]);
            #pragma unroll
            for (int rr = 0; rr < 8; rr++)
                #pragma unroll
                for (int ff = 0; ff < 8; ff++)
                    acc[rr][ff] = fmaf(wr[rr], hr[ff], acc[rr][ff]);
        }
    }

    // write partials (exclusive region per block: no races, no atomics)
    #pragma unroll
    for (int rr = 0; rr < 8; rr++) {
        const int row = i0 + tr * 8 + rr;
        float4 v0, v1;
        v0.x = acc[rr][0]; v0.y = acc[rr][1]; v0.z = acc[rr][2]; v0.w = acc[rr][3];
        v1.x = acc[rr][4]; v1.y = acc[rr][5]; v1.z = acc[rr][6]; v1.w = acc[rr][7];
        *reinterpret_cast<float4*>(&g_pnum[split][(size_t)row * FOUT + tc * 8])     = v0;
        *reinterpret_cast<float4*>(&g_pnum[split][(size_t)row * FOUT + tc * 8 + 4]) = v1;
    }
    if (tid < BI) g_pden[split][i0 + tid] = myden;
}

// ---------------------------------------------------------------------------
// Kernel 3: combine splits, normalize, ELU
// ---------------------------------------------------------------------------
__global__ __launch_bounds__(256) void k_final(float* __restrict__ out) {
    const int idx = blockIdx.x * 256 + threadIdx.x;     // over N*FOUT
    const int row = idx >> 7;
    float num = g_pnum[0][idx] + g_pnum[1][idx] + g_pnum[2][idx] + g_pnum[3][idx];
    float den = g_pden[0][row] + g_pden[1][row] + g_pden[2][row] + g_pden[3][row];
    float h = num / den;
    out[idx] = h > 0.0f ? h : expm1f(h);
}

// ---------------------------------------------------------------------------
extern "C" void kernel_launch(void* const* d_in, const int* in_sizes, int n_in,
                              void* d_out, int out_size) {
    const float* x   = (const float*)d_in[0];
    const int*   adj = (const int*)  d_in[1];
    const float* W   = (const float*)d_in[2];
    const float* a   = (const float*)d_in[3];
    float* out = (float*)d_out;

    k_wh<<<N / 16, 128>>>(x, W);
    k_s<<<N, 128>>>(a);
    dim3 g2(N / BI, NSPLIT);
    k_attn<<<g2, 128>>>(adj);
    k_final<<<(N * FOUT) / 256, 256>>>(out);
}

// round 3
// speedup vs baseline: 3.4155x; 3.4155x over previous
#include <cuda_runtime.h>
#include <math.h>
#include <stdint.h>

#define N     8192
#define FIN   256
#define FOUT  128
#define ALPHA 0.2f
#define NSPLIT 4
#define CH    32
#define NCHUNK ((N / NSPLIT) / CH)   // 64 chunks per CTA

// padded pitches (floats) for conflict-free fragment loads
#define BP 36

// dynamic SMEM layout (bytes)
#define ADJ0_OFF 0
#define ADJ1_OFF 16384
#define B0_OFF   32768
#define B1_OFF   (32768 + 18432)
#define PS_OFF   (32768 + 2 * 18432)
#define SMEM_DYN (PS_OFF + 18432)     // 88064 B

// ---------------- scratch (device globals; no allocs allowed) ---------------
__device__ __align__(16) float g_WhT[FOUT * N];           // [f][j], tf32-rounded
__device__ float g_s1[N];
__device__ float g_s2[N];
__device__ __align__(16) float g_pnum[NSPLIT][N * FOUT];
__device__ float g_pden[NSPLIT][N];

// ---------------- helpers ----------------------------------------------------
__device__ __forceinline__ uint32_t smem_u32(const void* p) {
    uint32_t a;
    asm("{ .reg .u64 t; cvta.to.shared.u64 t, %1; cvt.u32.u64 %0, t; }" : "=r"(a) : "l"(p));
    return a;
}
__device__ __forceinline__ void cp_async16(uint32_t sa, const void* g) {
    asm volatile("cp.async.ca.shared.global [%0], [%1], 16;" :: "r"(sa), "l"(g) : "memory");
}
#define CP_COMMIT() asm volatile("cp.async.commit_group;" ::: "memory")
#define CP_WAIT(n)  asm volatile("cp.async.wait_group %0;" :: "n"(n) : "memory")

__device__ __forceinline__ float tf32_rna(float x) {
    uint32_t u;
    asm("cvt.rna.tf32.f32 %0, %1;" : "=r"(u) : "f"(x));
    return __uint_as_float(u);
}
__device__ __forceinline__ float wfun(float t, int ad) {
    float l = fmaxf(t, ALPHA * t);
    float e;
    asm("ex2.approx.f32 %0, %1;" : "=f"(e) : "f"(l * 1.4426950408889634f));
    e = (ad > 0) ? e : 0.0f;
    return tf32_rna(e);        // same rounded value feeds numerator AND denominator
}

// mma.sync m16n8k8 tf32: D(16x8) += A(16x8) * B(8x8)
__device__ __forceinline__ void mma_tf32(float* d, const uint32_t* a, const uint32_t* b) {
    asm volatile(
        "mma.sync.aligned.m16n8k8.row.col.f32.tf32.tf32.f32 "
        "{%0,%1,%2,%3}, {%4,%5,%6,%7}, {%8,%9}, {%0,%1,%2,%3};"
        : "+f"(d[0]), "+f"(d[1]), "+f"(d[2]), "+f"(d[3])
        : "r"(a[0]), "r"(a[1]), "r"(a[2]), "r"(a[3]), "r"(b[0]), "r"(b[1]));
}

// ---------------------------------------------------------------------------
// Kernel 1: WhT[f][j] = tf32_rna( (x @ W^T)[j][f] )
// ---------------------------------------------------------------------------
__global__ __launch_bounds__(128) void k_wh(const float* __restrict__ x,
                                            const float* __restrict__ W) {
    __shared__ __align__(16) float xs[16 * FIN];
    const int f  = threadIdx.x;
    const int r0 = blockIdx.x * 16;

    for (int idx = f; idx < 16 * FIN; idx += 128)
        xs[idx] = x[(size_t)r0 * FIN + idx];
    __syncthreads();

    float acc[16];
    #pragma unroll
    for (int r = 0; r < 16; r++) acc[r] = 0.0f;

    const float4* Wrow = reinterpret_cast<const float4*>(W + f * FIN);
    #pragma unroll 4
    for (int k4 = 0; k4 < FIN / 4; k4++) {
        float4 wv = Wrow[k4];
        #pragma unroll
        for (int r = 0; r < 16; r++) {
            float4 xv = *reinterpret_cast<const float4*>(&xs[r * FIN + k4 * 4]);
            acc[r] = fmaf(xv.x, wv.x, acc[r]);
            acc[r] = fmaf(xv.y, wv.y, acc[r]);
            acc[r] = fmaf(xv.z, wv.z, acc[r]);
            acc[r] = fmaf(xv.w, wv.w, acc[r]);
        }
    }
    __syncthreads();
    #pragma unroll
    for (int r = 0; r < 16; r++) xs[f * 16 + r] = tf32_rna(acc[r]);
    __syncthreads();
    #pragma unroll
    for (int k = 0; k < 16; k++) {
        int idx = f + k * 128;
        g_WhT[(size_t)(idx >> 4) * N + r0 + (idx & 15)] = xs[idx];
    }
}

// ---------------------------------------------------------------------------
// Kernel 1b: s1/s2 from WhT (coalesced along j)
// ---------------------------------------------------------------------------
__global__ __launch_bounds__(128) void k_s(const float* __restrict__ a) {
    const int r = blockIdx.x * 128 + threadIdx.x;
    float a1 = 0.0f, a2 = 0.0f;
    #pragma unroll 8
    for (int f = 0; f < FOUT; f++) {
        float w = g_WhT[(size_t)f * N + r];
        a1 = fmaf(w, __ldg(&a[f]), a1);
        a2 = fmaf(w, __ldg(&a[FOUT + f]), a2);
    }
    g_s1[r] = a1;
    g_s2[r] = a2;
}

// ---------------------------------------------------------------------------
// Kernel 2: attention GEMM via mma.sync tf32.
// CTA: 256 thr (8 warps), i-tile = 128, full FOUT, j range N/NSPLIT.
// cp.async double-buffers adj + B tiles; P built per chunk; warp tiles 64x32.
// ---------------------------------------------------------------------------
__global__ __launch_bounds__(256, 2) void k_attn(const int* __restrict__ adj) {
    extern __shared__ char smem[];
    const uint32_t sb = smem_u32(smem);

    const int tid   = threadIdx.x;
    const int lane  = tid & 31;
    const int wid   = tid >> 5;
    const int i0    = blockIdx.x * 128;
    const int split = blockIdx.y;
    const int jbeg  = split * (N / NSPLIT);

    // --- cp.async source/dest mapping (4 adj + 4 B segments per thread) ---
    const int seg_row = tid >> 3;        // +32 per u (adj/B row index)
    const int seg_c   = tid & 7;         // 16B column within row

    // --- P-gen mapping: 4 rows x 4 cols per thread ---
    const int jg    = tid & 7;
    const int rbase = (tid >> 3) * 4;
    const float4 s1v = *reinterpret_cast<const float4*>(&g_s1[i0 + rbase]);

    // --- MMA warp tiling ---
    const int warp_m = (wid & 1) * 64;
    const int warp_n = (wid >> 1) * 32;
    const int qr = lane >> 2;       // quad row 0..7
    const int qc = lane & 3;        // quad col 0..3

    float acc[4][4][4];
    #pragma unroll
    for (int mt = 0; mt < 4; mt++)
        #pragma unroll
        for (int nt = 0; nt < 4; nt++)
            #pragma unroll
            for (int q = 0; q < 4; q++) acc[mt][nt][q] = 0.0f;

    float ds0 = 0.f, ds1 = 0.f, ds2 = 0.f, ds3 = 0.f;

    // prologue: stage chunk 0
    {
        const int j0 = jbeg;
        #pragma unroll
        for (int u = 0; u < 4; u++) {
            int r = seg_row + u * 32;
            cp_async16(sb + ADJ0_OFF + r * 128 + seg_c * 16,
                       adj + (size_t)(i0 + r) * N + j0 + seg_c * 4);
            cp_async16(sb + B0_OFF + r * (BP * 4) + seg_c * 16,
                       g_WhT + (size_t)r * N + j0 + seg_c * 4);
        }
        CP_COMMIT();
    }

    for (int c = 0; c < NCHUNK; c++) {
        const int bi = c & 1;
        const uint32_t adjb = sb + (bi ? ADJ1_OFF : ADJ0_OFF);
        const uint32_t bb   = sb + (bi ? B1_OFF : B0_OFF);
        const int j0 = jbeg + c * CH;

        if (c + 1 < NCHUNK) {    // stage next chunk into other buffer
            const int jn = j0 + CH;
            const uint32_t adjn = sb + (bi ? ADJ0_OFF : ADJ1_OFF);
            const uint32_t bn   = sb + (bi ? B0_OFF : B1_OFF);
            #pragma unroll
            for (int u = 0; u < 4; u++) {
                int r = seg_row + u * 32;
                cp_async16(adjn + r * 128 + seg_c * 16,
                           adj + (size_t)(i0 + r) * N + jn + seg_c * 4);
                cp_async16(bn + r * (BP * 4) + seg_c * 16,
                           g_WhT + (size_t)r * N + jn + seg_c * 4);
            }
            CP_COMMIT();
            CP_WAIT(1);          // chunk c resident, chunk c+1 in flight
        } else {
            CP_WAIT(0);
        }
        __syncthreads();

        // ---- P-gen: masked exp weights -> Ps, accumulate denominators ----
        const float4 s2v = *reinterpret_cast<const float4*>(&g_s2[j0 + jg * 4]);
        const float* Ab = reinterpret_cast<const float*>(smem);  // unused, silence
        (void)Ab;
        {
            const char* ap = (const char*)smem + (adjb - sb);
            char* pp = (char*)smem + PS_OFF;
            #pragma unroll
            for (int rr = 0; rr < 4; rr++) {
                int4 av = *(const int4*)(ap + (rbase + rr) * 128 + jg * 16);
                float s1 = (rr == 0) ? s1v.x : (rr == 1) ? s1v.y : (rr == 2) ? s1v.z : s1v.w;
                float w0 = wfun(s1 + s2v.x, av.x);
                float w1 = wfun(s1 + s2v.y, av.y);
                float w2 = wfun(s1 + s2v.z, av.z);
                float w3 = wfun(s1 + s2v.w, av.w);
                float d = (w0 + w1) + (w2 + w3);
                if (rr == 0) ds0 += d; else if (rr == 1) ds1 += d;
                else if (rr == 2) ds2 += d; else ds3 += d;
                *(float4*)(pp + (rbase + rr) * (BP * 4) + jg * 16) = make_float4(w0, w1, w2, w3);
            }
        }
        __syncthreads();

        // ---- MMA: 4 k-steps of 8 ----
        const float* Ps = reinterpret_cast<const float*>((const char*)smem + PS_OFF);
        const float* Bs = reinterpret_cast<const float*>((const char*)smem + (bb - sb));
        #pragma unroll
        for (int ks = 0; ks < 4; ks++) {
            const int k0 = ks * 8;
            uint32_t bf[4][2];
            #pragma unroll
            for (int nt = 0; nt < 4; nt++) {
                const float* bp = Bs + (warp_n + nt * 8 + qr) * BP + k0 + qc;
                bf[nt][0] = __float_as_uint(bp[0]);
                bf[nt][1] = __float_as_uint(bp[4]);
            }
            #pragma unroll
            for (int mt = 0; mt < 4; mt++) {
                const float* a0p = Ps + (warp_m + mt * 16 + qr) * BP + k0 + qc;
                const float* a1p = a0p + 8 * BP;
                uint32_t af[4];
                af[0] = __float_as_uint(a0p[0]);
                af[1] = __float_as_uint(a1p[0]);
                af[2] = __float_as_uint(a0p[4]);
                af[3] = __float_as_uint(a1p[4]);
                #pragma unroll
                for (int nt = 0; nt < 4; nt++)
                    mma_tf32(acc[mt][nt], af, bf[nt]);
            }
        }
        __syncthreads();   // Ps/Bs[bi] consumed before overwrite
    }

    // ---- denominators ----
    {
        float ds[4] = {ds0, ds1, ds2, ds3};
        #pragma unroll
        for (int rr = 0; rr < 4; rr++) {
            float v = ds[rr];
            v += __shfl_down_sync(0xffffffffu, v, 4, 8);
            v += __shfl_down_sync(0xffffffffu, v, 2, 8);
            v += __shfl_down_sync(0xffffffffu, v, 1, 8);
            if (jg == 0) g_pden[split][i0 + rbase + rr] = v;
        }
    }

    // ---- numerators: write accumulator fragments ----
    float* pn = g_pnum[split];
    #pragma unroll
    for (int mt = 0; mt < 4; mt++) {
        const int row0 = i0 + warp_m + mt * 16 + qr;
        #pragma unroll
        for (int nt = 0; nt < 4; nt++) {
            const int col = warp_n + nt * 8 + 2 * qc;
            *(float2*)(pn + (size_t)row0 * FOUT + col) =
                make_float2(acc[mt][nt][0], acc[mt][nt][1]);
            *(float2*)(pn + (size_t)(row0 + 8) * FOUT + col) =
                make_float2(acc[mt][nt][2], acc[mt][nt][3]);
        }
    }
}

// ---------------------------------------------------------------------------
// Kernel 3: combine splits, normalize, ELU
// ---------------------------------------------------------------------------
__global__ __launch_bounds__(256) void k_final(float* __restrict__ out) {
    const int idx = blockIdx.x * 256 + threadIdx.x;
    const int row = idx >> 7;
    float num = g_pnum[0][idx] + g_pnum[1][idx] + g_pnum[2][idx] + g_pnum[3][idx];
    float den = g_pden[0][row] + g_pden[1][row] + g_pden[2][row] + g_pden[3][row];
    float h = num / den;
    out[idx] = h > 0.0f ? h : expm1f(h);
}

// ---------------------------------------------------------------------------
extern "C" void kernel_launch(void* const* d_in, const int* in_sizes, int n_in,
                              void* d_out, int out_size) {
    const float* x   = (const float*)d_in[0];
    const int*   adj = (const int*)  d_in[1];
    const float* W   = (const float*)d_in[2];
    const float* a   = (const float*)d_in[3];
    float* out = (float*)d_out;

    cudaFuncSetAttribute(k_attn, cudaFuncAttributeMaxDynamicSharedMemorySize, SMEM_DYN);

    k_wh<<<N / 16, 128>>>(x, W);
    k_s<<<N / 128, 128>>>(a);
    dim3 g2(N / 128, NSPLIT);
    k_attn<<<g2, 256, SMEM_DYN>>>(adj);
    k_final<<<(N * FOUT) / 256, 256>>>(out);
}

// round 4
// speedup vs baseline: 3.7524x; 1.0986x over previous
#include <cuda_runtime.h>
#include <math.h>
#include <stdint.h>

#define N     8192
#define FIN   256
#define FOUT  128
#define ALPHA 0.2f
#define NSPLIT 4
#define CH    32
#define NCHUNK ((N / NSPLIT) / CH)   // 64 chunks per CTA

#define PITCH 144                     // staged row pitch (bytes) = 9 x 16B

// dynamic SMEM layout (bytes)
#define S2_OFF   0
#define ADJ0_OFF 8192
#define ADJ1_OFF (8192 + 18432)
#define B0_OFF   (8192 + 2 * 18432)
#define B1_OFF   (8192 + 3 * 18432)
#define SMEM_DYN (8192 + 4 * 18432)   // 81920 B

// ---------------- scratch (device globals; no allocs allowed) ---------------
__device__ __align__(16) float g_WhT[FOUT * N];   // [f][perm(j)], tf32-rounded
__device__ float g_s1[N];
__device__ float g_s2[N];
__device__ __align__(16) float g_pnum[NSPLIT][N * FOUT];
__device__ float g_pden[NSPLIT][N];

// ---------------- helpers ----------------------------------------------------
__device__ __host__ __forceinline__ int permj(int j) {
    // permute within each 32-col block: p = (j%4)*8 + (j/4)%8
    return (j & ~31) | (((j & 3) << 3) | ((j & 31) >> 2));
}
__device__ __forceinline__ uint32_t smem_u32(const void* p) {
    uint32_t a;
    asm("{ .reg .u64 t; cvta.to.shared.u64 t, %1; cvt.u32.u64 %0, t; }" : "=r"(a) : "l"(p));
    return a;
}
__device__ __forceinline__ void cp_async16(uint32_t sa, const void* g) {
    asm volatile("cp.async.ca.shared.global [%0], [%1], 16;" :: "r"(sa), "l"(g) : "memory");
}
#define CP_COMMIT() asm volatile("cp.async.commit_group;" ::: "memory")
#define CP_WAIT(n)  asm volatile("cp.async.wait_group %0;" :: "n"(n) : "memory")

__device__ __forceinline__ float tf32_rna(float x) {
    uint32_t u;
    asm("cvt.rna.tf32.f32 %0, %1;" : "=r"(u) : "f"(x));
    return __uint_as_float(u);
}
__device__ __forceinline__ float wfun(float t, int ad) {
    float l = fmaxf(t, ALPHA * t);
    float e;
    asm("ex2.approx.f32 %0, %1;" : "=f"(e) : "f"(l * 1.4426950408889634f));
    e = (ad > 0) ? e : 0.0f;
    return tf32_rna(e);     // same rounded value feeds numerator AND denominator
}

__device__ __forceinline__ void mma_tf32(float* d, const float* a, float b0, float b1) {
    asm volatile(
        "mma.sync.aligned.m16n8k8.row.col.f32.tf32.tf32.f32 "
        "{%0,%1,%2,%3}, {%4,%5,%6,%7}, {%8,%9}, {%0,%1,%2,%3};"
        : "+f"(d[0]), "+f"(d[1]), "+f"(d[2]), "+f"(d[3])
        : "r"(__float_as_uint(a[0])), "r"(__float_as_uint(a[1])),
          "r"(__float_as_uint(a[2])), "r"(__float_as_uint(a[3])),
          "r"(__float_as_uint(b0)), "r"(__float_as_uint(b1)));
}

// ---------------------------------------------------------------------------
// Kernel 1: WhT[f][perm(j)] = tf32_rna( (x @ W^T)[j][f] )
// ---------------------------------------------------------------------------
__global__ __launch_bounds__(128) void k_wh(const float* __restrict__ x,
                                            const float* __restrict__ W) {
    __shared__ __align__(16) float xs[16 * FIN];
    const int f  = threadIdx.x;
    const int r0 = blockIdx.x * 16;

    for (int idx = f; idx < 16 * FIN; idx += 128)
        xs[idx] = x[(size_t)r0 * FIN + idx];
    __syncthreads();

    float acc[16];
    #pragma unroll
    for (int r = 0; r < 16; r++) acc[r] = 0.0f;

    const float4* Wrow = reinterpret_cast<const float4*>(W + f * FIN);
    #pragma unroll 4
    for (int k4 = 0; k4 < FIN / 4; k4++) {
        float4 wv = Wrow[k4];
        #pragma unroll
        for (int r = 0; r < 16; r++) {
            float4 xv = *reinterpret_cast<const float4*>(&xs[r * FIN + k4 * 4]);
            acc[r] = fmaf(xv.x, wv.x, acc[r]);
            acc[r] = fmaf(xv.y, wv.y, acc[r]);
            acc[r] = fmaf(xv.z, wv.z, acc[r]);
            acc[r] = fmaf(xv.w, wv.w, acc[r]);
        }
    }
    __syncthreads();
    #pragma unroll
    for (int r = 0; r < 16; r++) xs[f * 16 + r] = tf32_rna(acc[r]);
    __syncthreads();
    #pragma unroll
    for (int k = 0; k < 16; k++) {
        int idx = f + k * 128;
        int fo = idx >> 4, ro = idx & 15;
        int within = (r0 & 16) + ro;
        int p = ((within & 3) << 3) | (within >> 2);
        g_WhT[(size_t)fo * N + (r0 & ~31) + p] = xs[idx];
    }
}

// ---------------------------------------------------------------------------
// Kernel 1b: s1/s2 from WhT (permuted columns)
// ---------------------------------------------------------------------------
__global__ __launch_bounds__(128) void k_s(const float* __restrict__ a) {
    const int r  = blockIdx.x * 128 + threadIdx.x;
    const int pr = permj(r);
    float a1 = 0.0f, a2 = 0.0f;
    #pragma unroll 8
    for (int f = 0; f < FOUT; f++) {
        float w = g_WhT[(size_t)f * N + pr];
        a1 = fmaf(w, __ldg(&a[f]), a1);
        a2 = fmaf(w, __ldg(&a[FOUT + f]), a2);
    }
    g_s1[r] = a1;
    g_s2[r] = a2;
}

// ---------------------------------------------------------------------------
// Kernel 2: attention GEMM via mma.sync tf32, P built in A-fragment registers.
// 8 warps, warp tile = 16 (i) x 128 (f). adj+B double-buffered via cp.async.
// ---------------------------------------------------------------------------
__global__ __launch_bounds__(256, 2) void k_attn(const int* __restrict__ adj) {
    extern __shared__ char smem[];
    const uint32_t sb = smem_u32(smem);
    float* const s2s = reinterpret_cast<float*>(smem + S2_OFF);

    const int tid   = threadIdx.x;
    const int lane  = tid & 31;
    const int wid   = tid >> 5;
    const int i0    = blockIdx.x * 128;
    const int split = blockIdx.y;
    const int jbeg  = split * (N / NSPLIT);

    // persistent s2 tile for this CTA's j-range
    {
        const float4* src = reinterpret_cast<const float4*>(g_s2 + jbeg);
        float4* dst = reinterpret_cast<float4*>(s2s);
        #pragma unroll
        for (int u = 0; u < 2; u++) dst[tid + u * 256] = src[tid + u * 256];
    }

    // cp.async mapping: 4 adj rows + 4 B rows per thread per chunk
    const int seg_row = tid >> 3;
    const int seg_c   = tid & 7;

    // MMA fragment mapping
    const int qr = lane >> 2;       // 0..7
    const int qc = lane & 3;        // 0..3
    const int warp_m = wid * 16;
    const float s1a = g_s1[i0 + warp_m + qr];
    const float s1b = g_s1[i0 + warp_m + qr + 8];
    const uint32_t rowa = (uint32_t)(warp_m + qr) * PITCH;
    const uint32_t rowb = rowa + 8 * PITCH;

    float acc[16][4];
    #pragma unroll
    for (int nt = 0; nt < 16; nt++)
        #pragma unroll
        for (int q = 0; q < 4; q++) acc[nt][q] = 0.0f;
    float dsa = 0.f, dsb = 0.f;

    // prologue: stage chunk 0
    #pragma unroll
    for (int u = 0; u < 4; u++) {
        int r = seg_row + u * 32;
        cp_async16(sb + ADJ0_OFF + r * PITCH + seg_c * 16,
                   adj + (size_t)(i0 + r) * N + jbeg + seg_c * 4);
        cp_async16(sb + B0_OFF + r * PITCH + seg_c * 16,
                   g_WhT + (size_t)r * N + jbeg + seg_c * 4);
    }
    CP_COMMIT();

    for (int c = 0; c < NCHUNK; c++) {
        const int bi = c & 1;
        const char* ap = smem + (bi ? ADJ1_OFF : ADJ0_OFF);
        const char* bp = smem + (bi ? B1_OFF : B0_OFF);

        if (c + 1 < NCHUNK) {
            const int jn = jbeg + (c + 1) * CH;
            const uint32_t adjn = sb + (bi ? ADJ0_OFF : ADJ1_OFF);
            const uint32_t bn   = sb + (bi ? B0_OFF : B1_OFF);
            #pragma unroll
            for (int u = 0; u < 4; u++) {
                int r = seg_row + u * 32;
                cp_async16(adjn + r * PITCH + seg_c * 16,
                           adj + (size_t)(i0 + r) * N + jn + seg_c * 4);
                cp_async16(bn + r * PITCH + seg_c * 16,
                           g_WhT + (size_t)r * N + jn + seg_c * 4);
            }
            CP_COMMIT();
            CP_WAIT(1);
        } else {
            CP_WAIT(0);
        }
        __syncthreads();

        // ---- A fragments (P weights) straight into registers ----
        float af[4][4];
        const float* s2c = s2s + c * CH;
        #pragma unroll
        for (int ks = 0; ks < 4; ks++) {
            const int ja = 8 * ks + qc;
            const int jb = ja + 4;
            int ad0 = *(const int*)(ap + rowa + ja * 4);
            int ad1 = *(const int*)(ap + rowb + ja * 4);
            int ad2 = *(const int*)(ap + rowa + jb * 4);
            int ad3 = *(const int*)(ap + rowb + jb * 4);
            float s2_0 = s2c[ja];
            float s2_1 = s2c[jb];
            af[ks][0] = wfun(s1a + s2_0, ad0);
            af[ks][1] = wfun(s1b + s2_0, ad1);
            af[ks][2] = wfun(s1a + s2_1, ad2);
            af[ks][3] = wfun(s1b + s2_1, ad3);
            dsa += af[ks][0] + af[ks][2];
            dsb += af[ks][1] + af[ks][3];
        }

        // ---- MMA: 16 n-tiles, B frags for all 4 k-steps as 2 x float4 ----
        #pragma unroll
        for (int nt = 0; nt < 16; nt++) {
            const char* brow = bp + (nt * 8 + qr) * PITCH + qc * 32;
            float4 v0 = *reinterpret_cast<const float4*>(brow);
            float4 v1 = *reinterpret_cast<const float4*>(brow + 16);
            mma_tf32(acc[nt], af[0], v0.x, v0.y);
            mma_tf32(acc[nt], af[1], v0.z, v0.w);
            mma_tf32(acc[nt], af[2], v1.x, v1.y);
            mma_tf32(acc[nt], af[3], v1.z, v1.w);
        }
        __syncthreads();   // all reads of buf bi done before it is restaged
    }

    // ---- denominators: reduce the 4 qc partials per row ----
    dsa += __shfl_xor_sync(0xffffffffu, dsa, 1);
    dsa += __shfl_xor_sync(0xffffffffu, dsa, 2);
    dsb += __shfl_xor_sync(0xffffffffu, dsb, 1);
    dsb += __shfl_xor_sync(0xffffffffu, dsb, 2);
    if (qc == 0) {
        g_pden[split][i0 + warp_m + qr]     = dsa;
        g_pden[split][i0 + warp_m + qr + 8] = dsb;
    }

    // ---- numerators ----
    float* pn = g_pnum[split];
    const int row0 = i0 + warp_m + qr;
    #pragma unroll
    for (int nt = 0; nt < 16; nt++) {
        const int col = nt * 8 + 2 * qc;
        *reinterpret_cast<float2*>(pn + (size_t)row0 * FOUT + col) =
            make_float2(acc[nt][0], acc[nt][1]);
        *reinterpret_cast<float2*>(pn + (size_t)(row0 + 8) * FOUT + col) =
            make_float2(acc[nt][2], acc[nt][3]);
    }
}

// ---------------------------------------------------------------------------
// Kernel 3: combine splits, normalize, ELU (vectorized)
// ---------------------------------------------------------------------------
__global__ __launch_bounds__(256) void k_final(float* __restrict__ out) {
    const int v   = blockIdx.x * 256 + threadIdx.x;   // float4 index
    const int row = v >> 5;
    const float4* p0 = reinterpret_cast<const float4*>(g_pnum[0]);
    const float4* p1 = reinterpret_cast<const float4*>(g_pnum[1]);
    const float4* p2 = reinterpret_cast<const float4*>(g_pnum[2]);
    const float4* p3 = reinterpret_cast<const float4*>(g_pnum[3]);
    float4 n0 = p0[v], n1 = p1[v], n2 = p2[v], n3 = p3[v];
    float den = g_pden[0][row] + g_pden[1][row] + g_pden[2][row] + g_pden[3][row];
    float inv = 1.0f / den;
    float4 h;
    h.x = (n0.x + n1.x + n2.x + n3.x) * inv;
    h.y = (n0.y + n1.y + n2.y + n3.y) * inv;
    h.z = (n0.z + n1.z + n2.z + n3.z) * inv;
    h.w = (n0.w + n1.w + n2.w + n3.w) * inv;
    h.x = h.x > 0.0f ? h.x : expm1f(h.x);
    h.y = h.y > 0.0f ? h.y : expm1f(h.y);
    h.z = h.z > 0.0f ? h.z : expm1f(h.z);
    h.w = h.w > 0.0f ? h.w : expm1f(h.w);
    reinterpret_cast<float4*>(out)[v] = h;
}

// ---------------------------------------------------------------------------
extern "C" void kernel_launch(void* const* d_in, const int* in_sizes, int n_in,
                              void* d_out, int out_size) {
    const float* x   = (const float*)d_in[0];
    const int*   adj = (const int*)  d_in[1];
    const float* W   = (const float*)d_in[2];
    const float* a   = (const float*)d_in[3];
    float* out = (float*)d_out;

    cudaFuncSetAttribute(k_attn, cudaFuncAttributeMaxDynamicSharedMemorySize, SMEM_DYN);

    k_wh<<<N / 16, 128>>>(x, W);
    k_s<<<N / 128, 128>>>(a);
    dim3 g2(N / 128, NSPLIT);
    k_attn<<<g2, 256, SMEM_DYN>>>(adj);
    k_final<<<(N * FOUT) / 1024, 256>>>(out);
}